// round 1
// baseline (speedup 1.0000x reference)
#include <cuda_runtime.h>
#include <math.h>

#define D_MODEL 512
#define D_FF 2048
#define BATCH 2
#define SEQ 2048
#define NHEADS 8
#define EDIM 64
#define ROWS (BATCH*SEQ)
#define GELU_CF 0.7978845608028654f

// ---------------- scratch (no allocation allowed; device globals) ----------------
__device__ float g_x[ROWS*D_MODEL];
__device__ float g_xb[ROWS*D_MODEL];
__device__ float g_q[ROWS*D_MODEL];
__device__ float g_k[ROWS*D_MODEL];
__device__ float g_v[ROWS*D_MODEL];
__device__ float g_attn[ROWS*D_MODEL];
__device__ float g_h[ROWS*D_FF];
__device__ float g_o[ROWS*D_MODEL];
__device__ float g_scores[(size_t)BATCH*NHEADS*SEQ*SEQ];  // 256 MB

// ---------------- GEMM: C[M,N] = A[M,K] @ W[K,N] + bias (+epilogue) ----------------
// epi: 0 = bias only, 1 = bias + add[], 2 = bias + gelu
__global__ __launch_bounds__(256) void gemm_k(
    const float* __restrict__ A, const float* __restrict__ W,
    const float* __restrict__ bias, const float* __restrict__ add,
    float* __restrict__ C, int M, int N, int K, int epi)
{
    __shared__ float sA[16][132];  // [k][m], padded
    __shared__ float sB[16][64];   // [k][n]
    const int bm = blockIdx.y * 128;
    const int bn = blockIdx.x * 64;
    const int tid = threadIdx.x;
    const int tx = tid & 15;
    const int ty = tid >> 4;

    float acc[8][4];
    #pragma unroll
    for (int i = 0; i < 8; i++)
        #pragma unroll
        for (int j = 0; j < 4; j++) acc[i][j] = 0.f;

    for (int kt = 0; kt < K; kt += 16) {
        #pragma unroll
        for (int i = 0; i < 8; i++) {
            int idx = tid + i * 256;       // 0..2047 over 128x16
            int r = idx >> 4, c = idx & 15;
            sA[c][r] = A[(size_t)(bm + r) * K + kt + c];
        }
        #pragma unroll
        for (int i = 0; i < 4; i++) {
            int idx = tid + i * 256;       // 0..1023 over 16x64
            int r = idx >> 6, c = idx & 63;
            sB[r][c] = W[(size_t)(kt + r) * N + bn + c];
        }
        __syncthreads();
        #pragma unroll
        for (int kk = 0; kk < 16; kk++) {
            float a[8], b[4];
            #pragma unroll
            for (int i = 0; i < 8; i++) a[i] = sA[kk][ty + i * 16];
            #pragma unroll
            for (int j = 0; j < 4; j++) b[j] = sB[kk][tx + j * 16];
            #pragma unroll
            for (int i = 0; i < 8; i++)
                #pragma unroll
                for (int j = 0; j < 4; j++)
                    acc[i][j] = fmaf(a[i], b[j], acc[i][j]);
        }
        __syncthreads();
    }

    #pragma unroll
    for (int i = 0; i < 8; i++) {
        int row = bm + ty + i * 16;
        #pragma unroll
        for (int j = 0; j < 4; j++) {
            int col = bn + tx + j * 16;
            float v = acc[i][j] + bias[col];
            if (epi == 1) {
                v += add[(size_t)row * N + col];
            } else if (epi == 2) {
                float u = v;
                v = 0.5f * u * (1.0f + tanhf(GELU_CF * (u + 0.044715f * u * u * u)));
            }
            C[(size_t)row * N + col] = v;
        }
    }
}

// ---------------- scores: S[bh,l,s] = scale*(q.k * tau[b] + delta[b,s]), causal ----------------
__global__ __launch_bounds__(256) void scores_k(
    const float* __restrict__ q, const float* __restrict__ k,
    const float* __restrict__ tau, const float* __restrict__ delta,
    float* __restrict__ S)
{
    const int st = blockIdx.x, lt = blockIdx.y;
    if (st > lt) return;                // fully-masked tile: never written, never read
    const int bh = blockIdx.z;
    const int b = bh >> 3, h = bh & 7;
    __shared__ float sQ[64][65];
    __shared__ float sK[64][65];
    const int tid = threadIdx.x;
    #pragma unroll
    for (int i = 0; i < 16; i++) {
        int idx = tid + i * 256;
        int r = idx >> 6, c = idx & 63;
        sQ[r][c] = q[(size_t)(b * SEQ + lt * 64 + r) * D_MODEL + h * EDIM + c];
        sK[r][c] = k[(size_t)(b * SEQ + st * 64 + r) * D_MODEL + h * EDIM + c];
    }
    __syncthreads();
    const int tx = tid & 15, ty = tid >> 4;
    float acc[4][4];
    #pragma unroll
    for (int i = 0; i < 4; i++)
        #pragma unroll
        for (int j = 0; j < 4; j++) acc[i][j] = 0.f;
    for (int e = 0; e < 64; e++) {
        float a[4], bb[4];
        #pragma unroll
        for (int i = 0; i < 4; i++) a[i] = sQ[ty + i * 16][e];
        #pragma unroll
        for (int j = 0; j < 4; j++) bb[j] = sK[tx + j * 16][e];
        #pragma unroll
        for (int i = 0; i < 4; i++)
            #pragma unroll
            for (int j = 0; j < 4; j++)
                acc[i][j] = fmaf(a[i], bb[j], acc[i][j]);
    }
    const float tb = tau[b];
    const float scl = 0.125f;   // 1/sqrt(E)
    #pragma unroll
    for (int i = 0; i < 4; i++) {
        int l = lt * 64 + ty + i * 16;
        #pragma unroll
        for (int j = 0; j < 4; j++) {
            int s = st * 64 + tx + j * 16;
            float v = scl * (acc[i][j] * tb + delta[b * SEQ + s]);
            if (s > l) v = -1e30f;
            S[((size_t)bh * SEQ + l) * SEQ + s] = v;
        }
    }
}

// ---------------- softmax: one block per row, register-resident ----------------
__global__ __launch_bounds__(256) void softmax_k(float* __restrict__ S)
{
    const int row = blockIdx.x;             // over BATCH*NHEADS*SEQ
    const int l = row & (SEQ - 1);
    const int n = ((l >> 6) + 1) << 6;      // causal tile-rounded length
    float* p = S + (size_t)row * SEQ;
    const int tid = threadIdx.x;
    float vals[8];
    float mx = -3e38f;
    #pragma unroll
    for (int i = 0; i < 8; i++) {
        int idx = tid + i * 256;
        vals[i] = (idx < n) ? p[idx] : -3e38f;
        mx = fmaxf(mx, vals[i]);
    }
    __shared__ float shm[8];
    __shared__ float shs[8];
    #pragma unroll
    for (int o = 16; o > 0; o >>= 1) mx = fmaxf(mx, __shfl_xor_sync(~0u, mx, o));
    if ((tid & 31) == 0) shm[tid >> 5] = mx;
    __syncthreads();
    mx = shm[0];
    #pragma unroll
    for (int w = 1; w < 8; w++) mx = fmaxf(mx, shm[w]);

    float sum = 0.f;
    #pragma unroll
    for (int i = 0; i < 8; i++) {
        int idx = tid + i * 256;
        float e = (idx < n) ? expf(vals[i] - mx) : 0.f;
        vals[i] = e;
        sum += e;
    }
    #pragma unroll
    for (int o = 16; o > 0; o >>= 1) sum += __shfl_xor_sync(~0u, sum, o);
    if ((tid & 31) == 0) shs[tid >> 5] = sum;
    __syncthreads();
    sum = shs[0] + shs[1] + shs[2] + shs[3] + shs[4] + shs[5] + shs[6] + shs[7];
    const float inv = 1.0f / sum;
    #pragma unroll
    for (int i = 0; i < 8; i++) {
        int idx = tid + i * 256;
        if (idx < n) p[idx] = vals[i] * inv;
    }
}

// ---------------- A@V: out[b,l,h,:] = sum_s P[bh,l,s] * v[b,s,h,:] ----------------
__global__ __launch_bounds__(256) void av_k(
    const float* __restrict__ S, const float* __restrict__ V,
    float* __restrict__ out)
{
    const int lt = blockIdx.x;
    const int bh = blockIdx.y;
    const int b = bh >> 3, h = bh & 7;
    __shared__ float sP[64][65];
    __shared__ float sV[64][65];
    const int tid = threadIdx.x;
    const int tx = tid & 15, ty = tid >> 4;
    float acc[4][4];
    #pragma unroll
    for (int i = 0; i < 4; i++)
        #pragma unroll
        for (int j = 0; j < 4; j++) acc[i][j] = 0.f;

    for (int st = 0; st <= lt; st++) {
        #pragma unroll
        for (int i = 0; i < 16; i++) {
            int idx = tid + i * 256;
            int r = idx >> 6, c = idx & 63;
            sP[r][c] = S[((size_t)bh * SEQ + lt * 64 + r) * SEQ + st * 64 + c];
            sV[r][c] = V[(size_t)(b * SEQ + st * 64 + r) * D_MODEL + h * EDIM + c];
        }
        __syncthreads();
        for (int kk = 0; kk < 64; kk++) {
            float a[4], bb[4];
            #pragma unroll
            for (int i = 0; i < 4; i++) a[i] = sP[ty + i * 16][kk];
            #pragma unroll
            for (int j = 0; j < 4; j++) bb[j] = sV[kk][tx + j * 16];
            #pragma unroll
            for (int i = 0; i < 4; i++)
                #pragma unroll
                for (int j = 0; j < 4; j++)
                    acc[i][j] = fmaf(a[i], bb[j], acc[i][j]);
        }
        __syncthreads();
    }
    #pragma unroll
    for (int i = 0; i < 4; i++)
        #pragma unroll
        for (int j = 0; j < 4; j++)
            out[(size_t)(b * SEQ + lt * 64 + ty + i * 16) * D_MODEL + h * EDIM + tx + j * 16] = acc[i][j];
}

// ---------------- LayerNorm: one block (128 thr) per row of 512 ----------------
__global__ __launch_bounds__(128) void ln_k(
    const float* __restrict__ x, const float* __restrict__ g,
    const float* __restrict__ bb, float* __restrict__ y)
{
    const int row = blockIdx.x;
    const float* p = x + (size_t)row * D_MODEL;
    const int tid = threadIdx.x;
    float v[4];
    float s = 0.f;
    #pragma unroll
    for (int i = 0; i < 4; i++) { v[i] = p[tid + i * 128]; s += v[i]; }
    __shared__ float sh[4];
    #pragma unroll
    for (int o = 16; o > 0; o >>= 1) s += __shfl_xor_sync(~0u, s, o);
    if ((tid & 31) == 0) sh[tid >> 5] = s;
    __syncthreads();
    s = sh[0] + sh[1] + sh[2] + sh[3];
    const float mean = s * (1.0f / (float)D_MODEL);
    float vs = 0.f;
    #pragma unroll
    for (int i = 0; i < 4; i++) { float d = v[i] - mean; vs += d * d; }
    #pragma unroll
    for (int o = 16; o > 0; o >>= 1) vs += __shfl_xor_sync(~0u, vs, o);
    __syncthreads();
    if ((tid & 31) == 0) sh[tid >> 5] = vs;
    __syncthreads();
    vs = sh[0] + sh[1] + sh[2] + sh[3];
    const float rstd = rsqrtf(vs * (1.0f / (float)D_MODEL) + 1e-5f);
    #pragma unroll
    for (int i = 0; i < 4; i++) {
        int col = tid + i * 128;
        y[(size_t)row * D_MODEL + col] = (v[i] - mean) * rstd * g[col] + bb[col];
    }
}

// ---------------- orchestration ----------------
extern "C" void kernel_launch(void* const* d_in, const int* in_sizes, int n_in,
                              void* d_out, int out_size)
{
    const float* x_in  = (const float*)d_in[0];
    const float* tau   = (const float*)d_in[1];
    const float* delta = (const float*)d_in[2];
    // d_in[3] = att_mask (bool) — causal, reconstructed analytically
    const float* Wq = (const float*)d_in[4];
    const float* bq = (const float*)d_in[5];
    const float* Wk = (const float*)d_in[6];
    const float* bk = (const float*)d_in[7];
    const float* Wv = (const float*)d_in[8];
    const float* bv = (const float*)d_in[9];
    const float* Wo = (const float*)d_in[10];
    const float* bo = (const float*)d_in[11];
    const float* W1 = (const float*)d_in[12];
    const float* b1 = (const float*)d_in[13];
    const float* W2 = (const float*)d_in[14];
    const float* b2 = (const float*)d_in[15];
    const float* ln1g = (const float*)d_in[16];
    const float* ln1b = (const float*)d_in[17];
    const float* ln2g = (const float*)d_in[18];
    const float* ln2b = (const float*)d_in[19];
    const float* lnfg = (const float*)d_in[20];
    const float* lnfb = (const float*)d_in[21];

    float *gx, *gxb, *gq, *gk, *gv, *gattn, *gh, *go, *gS;
    cudaGetSymbolAddress((void**)&gx,    g_x);
    cudaGetSymbolAddress((void**)&gxb,   g_xb);
    cudaGetSymbolAddress((void**)&gq,    g_q);
    cudaGetSymbolAddress((void**)&gk,    g_k);
    cudaGetSymbolAddress((void**)&gv,    g_v);
    cudaGetSymbolAddress((void**)&gattn, g_attn);
    cudaGetSymbolAddress((void**)&gh,    g_h);
    cudaGetSymbolAddress((void**)&go,    g_o);
    cudaGetSymbolAddress((void**)&gS,    g_scores);

    cudaMemcpyAsync(gx, x_in, sizeof(float) * ROWS * D_MODEL,
                    cudaMemcpyDeviceToDevice, 0);

    const dim3 gProj(D_MODEL / 64, ROWS / 128);   // (8, 32)
    const dim3 gFF1(D_FF / 64, ROWS / 128);       // (32, 32)

    for (int l = 0; l < 2; l++) {
        const size_t wOff  = (size_t)l * D_MODEL * D_MODEL;
        const size_t bOff  = (size_t)l * D_MODEL;
        const size_t w1Off = (size_t)l * D_MODEL * D_FF;
        const size_t b1Off = (size_t)l * D_FF;
        const size_t w2Off = (size_t)l * D_FF * D_MODEL;

        gemm_k<<<gProj, 256>>>(gx, Wq + wOff, bq + bOff, nullptr, gq,
                               ROWS, D_MODEL, D_MODEL, 0);
        gemm_k<<<gProj, 256>>>(gx, Wk + wOff, bk + bOff, nullptr, gk,
                               ROWS, D_MODEL, D_MODEL, 0);
        gemm_k<<<gProj, 256>>>(gx, Wv + wOff, bv + bOff, nullptr, gv,
                               ROWS, D_MODEL, D_MODEL, 0);

        scores_k<<<dim3(SEQ / 64, SEQ / 64, BATCH * NHEADS), 256>>>(gq, gk, tau, delta, gS);
        softmax_k<<<BATCH * NHEADS * SEQ, 256>>>(gS);
        av_k<<<dim3(SEQ / 64, BATCH * NHEADS), 256>>>(gS, gv, gattn);

        // x = attn @ Wo + bo + x
        gemm_k<<<gProj, 256>>>(gattn, Wo + wOff, bo + bOff, gx, gx,
                               ROWS, D_MODEL, D_MODEL, 1);
        ln_k<<<ROWS, 128>>>(gx, ln1g + bOff, ln1b + bOff, gxb);
        // h = gelu(xb @ W1 + b1)
        gemm_k<<<gFF1, 256>>>(gxb, W1 + w1Off, b1 + b1Off, nullptr, gh,
                              ROWS, D_FF, D_MODEL, 2);
        // o = h @ W2 + b2 + xb
        gemm_k<<<gProj, 256>>>(gh, W2 + w2Off, b2 + bOff, gxb, go,
                               ROWS, D_MODEL, D_FF, 1);
        ln_k<<<ROWS, 128>>>(go, ln2g + bOff, ln2b + bOff, gx);
    }
    ln_k<<<ROWS, 128>>>(gx, lnfg, lnfb, (float*)d_out);
}

// round 3
// speedup vs baseline: 1.6335x; 1.6335x over previous
#include <cuda_runtime.h>
#include <cuda_bf16.h>
#include <math.h>
#include <stdint.h>

#define D_MODEL 512
#define D_FF 2048
#define BATCH 2
#define SEQ 2048
#define NHEADS 8
#define EDIM 64
#define ROWS (BATCH*SEQ)
#define GELU_CF 0.7978845608028654f

// ---------------- scratch (no allocation allowed; device globals) ----------------
__device__ float g_x[ROWS*D_MODEL];
__device__ float g_xb[ROWS*D_MODEL];
__device__ float g_q[ROWS*D_MODEL];
__device__ float g_k[ROWS*D_MODEL];
__device__ float g_v[ROWS*D_MODEL];
__device__ float g_attn[ROWS*D_MODEL];
__device__ float g_h[ROWS*D_FF];
__device__ float g_o[ROWS*D_MODEL];
__device__ float g_scores[(size_t)BATCH*NHEADS*SEQ*SEQ];  // 256 MB

// =======================================================================
// bf16-split tensor-core GEMM (mma.sync m16n8k16, 3-product split)
// C[M,N] = A[M,K] @ W[K,N] + bias (+epilogue)
// Block tile 128x128, BK=32, 256 threads = 8 warps (2 x 4), warp tile 64x32.
// =======================================================================

#define A_PITCH 40    // bf16 elems per A smem row (32 + 8 pad) -> conflict-free frag loads
#define B_PITCH 136   // bf16 elems per B smem row (128 + 8 pad)

__device__ __forceinline__ void bsplit2(float x0, float x1, uint32_t& h, uint32_t& l) {
    __nv_bfloat162 hh = __floats2bfloat162_rn(x0, x1);
    float h0 = __bfloat162float(hh.x);
    float h1 = __bfloat162float(hh.y);
    __nv_bfloat162 ll = __floats2bfloat162_rn(x0 - h0, x1 - h1);
    h = *reinterpret_cast<uint32_t*>(&hh);
    l = *reinterpret_cast<uint32_t*>(&ll);
}

__device__ __forceinline__ void mma_bf16(float* c, const uint32_t* a, const uint32_t* b) {
    asm volatile(
        "mma.sync.aligned.m16n8k16.row.col.f32.bf16.bf16.f32 "
        "{%0,%1,%2,%3}, {%4,%5,%6,%7}, {%8,%9}, {%0,%1,%2,%3};"
        : "+f"(c[0]), "+f"(c[1]), "+f"(c[2]), "+f"(c[3])
        : "r"(a[0]), "r"(a[1]), "r"(a[2]), "r"(a[3]), "r"(b[0]), "r"(b[1]));
}

// epi: 0 = bias, 1 = bias + add[], 2 = bias + gelu
__global__ __launch_bounds__(256) void gemm_tc(
    const float* __restrict__ A, const float* __restrict__ W,
    const float* __restrict__ bias, const float* __restrict__ add,
    float* __restrict__ C, int N, int K, int epi)
{
    __shared__ uint16_t sAh[128 * A_PITCH];
    __shared__ uint16_t sAl[128 * A_PITCH];
    __shared__ uint16_t sBh[32 * B_PITCH];
    __shared__ uint16_t sBl[32 * B_PITCH];

    const int tid = threadIdx.x;
    const int wid = tid >> 5;
    const int lane = tid & 31;
    const int wm = wid & 1;     // 0..1 -> 64-row half
    const int wn = wid >> 1;    // 0..3 -> 32-col quarter
    const int fr = lane >> 2;        // 0..7
    const int fkc = (lane & 3) * 2;  // 0,2,4,6

    const int bm = blockIdx.y * 128;
    const int bn = blockIdx.x * 128;

    float acc[4][4][4];
    #pragma unroll
    for (int tm = 0; tm < 4; tm++)
        #pragma unroll
        for (int tn = 0; tn < 4; tn++)
            #pragma unroll
            for (int i = 0; i < 4; i++) acc[tm][tn][i] = 0.f;

    const int nChunks = K >> 5;

    // prefetch chunk 0
    float4 pa[4], pb[4];
    {
        #pragma unroll
        for (int i = 0; i < 4; i++) {
            int idx = tid + i * 256;            // 0..1023
            int row = idx >> 3, c4 = idx & 7;   // A: 128 rows x 8 float4
            pa[i] = *(const float4*)(A + (size_t)(bm + row) * K + c4 * 4);
            int kk = idx >> 5, n4 = idx & 31;   // B: 32 rows x 32 float4
            pb[i] = *(const float4*)(W + (size_t)kk * N + bn + n4 * 4);
        }
    }

    for (int chunk = 0; chunk < nChunks; chunk++) {
        // ---- convert + store current chunk to SMEM ----
        #pragma unroll
        for (int i = 0; i < 4; i++) {
            int idx = tid + i * 256;
            int row = idx >> 3, c4 = idx & 7;
            uint32_t h0, l0, h1, l1;
            bsplit2(pa[i].x, pa[i].y, h0, l0);
            bsplit2(pa[i].z, pa[i].w, h1, l1);
            int ao = row * A_PITCH + c4 * 4;
            *(uint32_t*)&sAh[ao]     = h0;  *(uint32_t*)&sAh[ao + 2] = h1;
            *(uint32_t*)&sAl[ao]     = l0;  *(uint32_t*)&sAl[ao + 2] = l1;

            int kk = idx >> 5, n4 = idx & 31;
            bsplit2(pb[i].x, pb[i].y, h0, l0);
            bsplit2(pb[i].z, pb[i].w, h1, l1);
            int bo = kk * B_PITCH + n4 * 4;
            *(uint32_t*)&sBh[bo]     = h0;  *(uint32_t*)&sBh[bo + 2] = h1;
            *(uint32_t*)&sBl[bo]     = l0;  *(uint32_t*)&sBl[bo + 2] = l1;
        }
        __syncthreads();

        // ---- prefetch next chunk ----
        if (chunk + 1 < nChunks) {
            int kt = (chunk + 1) << 5;
            #pragma unroll
            for (int i = 0; i < 4; i++) {
                int idx = tid + i * 256;
                int row = idx >> 3, c4 = idx & 7;
                pa[i] = *(const float4*)(A + (size_t)(bm + row) * K + kt + c4 * 4);
                int kk = idx >> 5, n4 = idx & 31;
                pb[i] = *(const float4*)(W + (size_t)(kt + kk) * N + bn + n4 * 4);
            }
        }

        // ---- compute: 2 k16 steps ----
        #pragma unroll
        for (int ks = 0; ks < 2; ks++) {
            const int K0 = ks * 16;
            uint32_t ah[4][4], al[4][4];
            #pragma unroll
            for (int tm = 0; tm < 4; tm++) {
                int base = (wm * 64 + tm * 16 + fr) * A_PITCH + K0 + fkc;
                ah[tm][0] = *(const uint32_t*)&sAh[base];
                ah[tm][1] = *(const uint32_t*)&sAh[base + 8 * A_PITCH];
                ah[tm][2] = *(const uint32_t*)&sAh[base + 8];
                ah[tm][3] = *(const uint32_t*)&sAh[base + 8 * A_PITCH + 8];
                al[tm][0] = *(const uint32_t*)&sAl[base];
                al[tm][1] = *(const uint32_t*)&sAl[base + 8 * A_PITCH];
                al[tm][2] = *(const uint32_t*)&sAl[base + 8];
                al[tm][3] = *(const uint32_t*)&sAl[base + 8 * A_PITCH + 8];
            }
            uint32_t bh[4][2], bl[4][2];
            #pragma unroll
            for (int tn = 0; tn < 4; tn++) {
                int n = wn * 32 + tn * 8 + fr;
                int kb = (K0 + fkc) * B_PITCH + n;
                bh[tn][0] = (uint32_t)sBh[kb] | ((uint32_t)sBh[kb + B_PITCH] << 16);
                bh[tn][1] = (uint32_t)sBh[kb + 8 * B_PITCH] | ((uint32_t)sBh[kb + 9 * B_PITCH] << 16);
                bl[tn][0] = (uint32_t)sBl[kb] | ((uint32_t)sBl[kb + B_PITCH] << 16);
                bl[tn][1] = (uint32_t)sBl[kb + 8 * B_PITCH] | ((uint32_t)sBl[kb + 9 * B_PITCH] << 16);
            }
            #pragma unroll
            for (int tm = 0; tm < 4; tm++)
                #pragma unroll
                for (int tn = 0; tn < 4; tn++)
                    mma_bf16(acc[tm][tn], ah[tm], bh[tn]);
            #pragma unroll
            for (int tm = 0; tm < 4; tm++)
                #pragma unroll
                for (int tn = 0; tn < 4; tn++)
                    mma_bf16(acc[tm][tn], ah[tm], bl[tn]);
            #pragma unroll
            for (int tm = 0; tm < 4; tm++)
                #pragma unroll
                for (int tn = 0; tn < 4; tn++)
                    mma_bf16(acc[tm][tn], al[tm], bh[tn]);
        }
        __syncthreads();
    }

    // ---- epilogue: direct float2 stores ----
    #pragma unroll
    for (int tm = 0; tm < 4; tm++) {
        #pragma unroll
        for (int tn = 0; tn < 4; tn++) {
            int row0 = bm + wm * 64 + tm * 16 + fr;
            int col = bn + wn * 32 + tn * 8 + fkc;
            float b0 = bias[col], b1 = bias[col + 1];
            #pragma unroll
            for (int half = 0; half < 2; half++) {
                int row = row0 + half * 8;
                float v0 = acc[tm][tn][half * 2 + 0] + b0;
                float v1 = acc[tm][tn][half * 2 + 1] + b1;
                if (epi == 1) {
                    const float* ap = add + (size_t)row * N + col;
                    v0 += ap[0]; v1 += ap[1];
                } else if (epi == 2) {
                    float u = v0;
                    v0 = 0.5f * u * (1.0f + tanhf(GELU_CF * (u + 0.044715f * u * u * u)));
                    u = v1;
                    v1 = 0.5f * u * (1.0f + tanhf(GELU_CF * (u + 0.044715f * u * u * u)));
                }
                float2 st = make_float2(v0, v1);
                *(float2*)(C + (size_t)row * N + col) = st;
            }
        }
    }
}

// ---------------- scores: S[bh,l,s] = scale*(q.k * tau[b] + delta[b,s]), causal ----------------
__global__ __launch_bounds__(256) void scores_k(
    const float* __restrict__ q, const float* __restrict__ k,
    const float* __restrict__ tau, const float* __restrict__ delta,
    float* __restrict__ S)
{
    const int st = blockIdx.x, lt = blockIdx.y;
    if (st > lt) return;
    const int bh = blockIdx.z;
    const int b = bh >> 3, h = bh & 7;
    __shared__ float sQ[64][65];
    __shared__ float sK[64][65];
    const int tid = threadIdx.x;
    #pragma unroll
    for (int i = 0; i < 16; i++) {
        int idx = tid + i * 256;
        int r = idx >> 6, c = idx & 63;
        sQ[r][c] = q[(size_t)(b * SEQ + lt * 64 + r) * D_MODEL + h * EDIM + c];
        sK[r][c] = k[(size_t)(b * SEQ + st * 64 + r) * D_MODEL + h * EDIM + c];
    }
    __syncthreads();
    const int tx = tid & 15, ty = tid >> 4;
    float acc[4][4];
    #pragma unroll
    for (int i = 0; i < 4; i++)
        #pragma unroll
        for (int j = 0; j < 4; j++) acc[i][j] = 0.f;
    for (int e = 0; e < 64; e++) {
        float a[4], bb[4];
        #pragma unroll
        for (int i = 0; i < 4; i++) a[i] = sQ[ty + i * 16][e];
        #pragma unroll
        for (int j = 0; j < 4; j++) bb[j] = sK[tx + j * 16][e];
        #pragma unroll
        for (int i = 0; i < 4; i++)
            #pragma unroll
            for (int j = 0; j < 4; j++)
                acc[i][j] = fmaf(a[i], bb[j], acc[i][j]);
    }
    const float tb = tau[b];
    const float scl = 0.125f;
    #pragma unroll
    for (int i = 0; i < 4; i++) {
        int l = lt * 64 + ty + i * 16;
        #pragma unroll
        for (int j = 0; j < 4; j++) {
            int s = st * 64 + tx + j * 16;
            float v = scl * (acc[i][j] * tb + delta[b * SEQ + s]);
            if (s > l) v = -1e30f;
            S[((size_t)bh * SEQ + l) * SEQ + s] = v;
        }
    }
}

// ---------------- softmax ----------------
__global__ __launch_bounds__(256) void softmax_k(float* __restrict__ S)
{
    const int row = blockIdx.x;
    const int l = row & (SEQ - 1);
    const int n = ((l >> 6) + 1) << 6;
    float* p = S + (size_t)row * SEQ;
    const int tid = threadIdx.x;
    float vals[8];
    float mx = -3e38f;
    #pragma unroll
    for (int i = 0; i < 8; i++) {
        int idx = tid + i * 256;
        vals[i] = (idx < n) ? p[idx] : -3e38f;
        mx = fmaxf(mx, vals[i]);
    }
    __shared__ float shm[8];
    __shared__ float shs[8];
    #pragma unroll
    for (int o = 16; o > 0; o >>= 1) mx = fmaxf(mx, __shfl_xor_sync(~0u, mx, o));
    if ((tid & 31) == 0) shm[tid >> 5] = mx;
    __syncthreads();
    mx = shm[0];
    #pragma unroll
    for (int w = 1; w < 8; w++) mx = fmaxf(mx, shm[w]);

    float sum = 0.f;
    #pragma unroll
    for (int i = 0; i < 8; i++) {
        int idx = tid + i * 256;
        float e = (idx < n) ? expf(vals[i] - mx) : 0.f;
        vals[i] = e;
        sum += e;
    }
    #pragma unroll
    for (int o = 16; o > 0; o >>= 1) sum += __shfl_xor_sync(~0u, sum, o);
    if ((tid & 31) == 0) shs[tid >> 5] = sum;
    __syncthreads();
    sum = shs[0] + shs[1] + shs[2] + shs[3] + shs[4] + shs[5] + shs[6] + shs[7];
    const float inv = 1.0f / sum;
    #pragma unroll
    for (int i = 0; i < 8; i++) {
        int idx = tid + i * 256;
        if (idx < n) p[idx] = vals[i] * inv;
    }
}

// ---------------- A@V ----------------
__global__ __launch_bounds__(256) void av_k(
    const float* __restrict__ S, const float* __restrict__ V,
    float* __restrict__ out)
{
    const int lt = blockIdx.x;
    const int bh = blockIdx.y;
    const int b = bh >> 3, h = bh & 7;
    __shared__ float sP[64][65];
    __shared__ float sV[64][65];
    const int tid = threadIdx.x;
    const int tx = tid & 15, ty = tid >> 4;
    float acc[4][4];
    #pragma unroll
    for (int i = 0; i < 4; i++)
        #pragma unroll
        for (int j = 0; j < 4; j++) acc[i][j] = 0.f;

    for (int st = 0; st <= lt; st++) {
        #pragma unroll
        for (int i = 0; i < 16; i++) {
            int idx = tid + i * 256;
            int r = idx >> 6, c = idx & 63;
            sP[r][c] = S[((size_t)bh * SEQ + lt * 64 + r) * SEQ + st * 64 + c];
            sV[r][c] = V[(size_t)(b * SEQ + st * 64 + r) * D_MODEL + h * EDIM + c];
        }
        __syncthreads();
        for (int kk = 0; kk < 64; kk++) {
            float a[4], bb[4];
            #pragma unroll
            for (int i = 0; i < 4; i++) a[i] = sP[ty + i * 16][kk];
            #pragma unroll
            for (int j = 0; j < 4; j++) bb[j] = sV[kk][tx + j * 16];
            #pragma unroll
            for (int i = 0; i < 4; i++)
                #pragma unroll
                for (int j = 0; j < 4; j++)
                    acc[i][j] = fmaf(a[i], bb[j], acc[i][j]);
        }
        __syncthreads();
    }
    #pragma unroll
    for (int i = 0; i < 4; i++)
        #pragma unroll
        for (int j = 0; j < 4; j++)
            out[(size_t)(b * SEQ + lt * 64 + ty + i * 16) * D_MODEL + h * EDIM + tx + j * 16] = acc[i][j];
}

// ---------------- LayerNorm ----------------
__global__ __launch_bounds__(128) void ln_k(
    const float* __restrict__ x, const float* __restrict__ g,
    const float* __restrict__ bb, float* __restrict__ y)
{
    const int row = blockIdx.x;
    const float* p = x + (size_t)row * D_MODEL;
    const int tid = threadIdx.x;
    float v[4];
    float s = 0.f;
    #pragma unroll
    for (int i = 0; i < 4; i++) { v[i] = p[tid + i * 128]; s += v[i]; }
    __shared__ float sh[4];
    #pragma unroll
    for (int o = 16; o > 0; o >>= 1) s += __shfl_xor_sync(~0u, s, o);
    if ((tid & 31) == 0) sh[tid >> 5] = s;
    __syncthreads();
    s = sh[0] + sh[1] + sh[2] + sh[3];
    const float mean = s * (1.0f / (float)D_MODEL);
    float vs = 0.f;
    #pragma unroll
    for (int i = 0; i < 4; i++) { float d = v[i] - mean; vs += d * d; }
    #pragma unroll
    for (int o = 16; o > 0; o >>= 1) vs += __shfl_xor_sync(~0u, vs, o);
    __syncthreads();
    if ((tid & 31) == 0) sh[tid >> 5] = vs;
    __syncthreads();
    vs = sh[0] + sh[1] + sh[2] + sh[3];
    const float rstd = rsqrtf(vs * (1.0f / (float)D_MODEL) + 1e-5f);
    #pragma unroll
    for (int i = 0; i < 4; i++) {
        int col = tid + i * 128;
        y[(size_t)row * D_MODEL + col] = (v[i] - mean) * rstd * g[col] + bb[col];
    }
}

// ---------------- orchestration ----------------
extern "C" void kernel_launch(void* const* d_in, const int* in_sizes, int n_in,
                              void* d_out, int out_size)
{
    const float* x_in  = (const float*)d_in[0];
    const float* tau   = (const float*)d_in[1];
    const float* delta = (const float*)d_in[2];
    const float* Wq = (const float*)d_in[4];
    const float* bq = (const float*)d_in[5];
    const float* Wk = (const float*)d_in[6];
    const float* bk = (const float*)d_in[7];
    const float* Wv = (const float*)d_in[8];
    const float* bv = (const float*)d_in[9];
    const float* Wo = (const float*)d_in[10];
    const float* bo = (const float*)d_in[11];
    const float* W1 = (const float*)d_in[12];
    const float* b1 = (const float*)d_in[13];
    const float* W2 = (const float*)d_in[14];
    const float* b2 = (const float*)d_in[15];
    const float* ln1g = (const float*)d_in[16];
    const float* ln1b = (const float*)d_in[17];
    const float* ln2g = (const float*)d_in[18];
    const float* ln2b = (const float*)d_in[19];
    const float* lnfg = (const float*)d_in[20];
    const float* lnfb = (const float*)d_in[21];

    float *gx, *gxb, *gq, *gk, *gv, *gattn, *gh, *go, *gS;
    cudaGetSymbolAddress((void**)&gx,    g_x);
    cudaGetSymbolAddress((void**)&gxb,   g_xb);
    cudaGetSymbolAddress((void**)&gq,    g_q);
    cudaGetSymbolAddress((void**)&gk,    g_k);
    cudaGetSymbolAddress((void**)&gv,    g_v);
    cudaGetSymbolAddress((void**)&gattn, g_attn);
    cudaGetSymbolAddress((void**)&gh,    g_h);
    cudaGetSymbolAddress((void**)&go,    g_o);
    cudaGetSymbolAddress((void**)&gS,    g_scores);

    cudaMemcpyAsync(gx, x_in, sizeof(float) * ROWS * D_MODEL,
                    cudaMemcpyDeviceToDevice, 0);

    const dim3 gProj(D_MODEL / 128, ROWS / 128);   // (4, 32)
    const dim3 gFF1(D_FF / 128, ROWS / 128);       // (16, 32)

    for (int l = 0; l < 2; l++) {
        const size_t wOff  = (size_t)l * D_MODEL * D_MODEL;
        const size_t bOff  = (size_t)l * D_MODEL;
        const size_t w1Off = (size_t)l * D_MODEL * D_FF;
        const size_t b1Off = (size_t)l * D_FF;
        const size_t w2Off = (size_t)l * D_FF * D_MODEL;

        gemm_tc<<<gProj, 256>>>(gx, Wq + wOff, bq + bOff, nullptr, gq,
                                D_MODEL, D_MODEL, 0);
        gemm_tc<<<gProj, 256>>>(gx, Wk + wOff, bk + bOff, nullptr, gk,
                                D_MODEL, D_MODEL, 0);
        gemm_tc<<<gProj, 256>>>(gx, Wv + wOff, bv + bOff, nullptr, gv,
                                D_MODEL, D_MODEL, 0);

        scores_k<<<dim3(SEQ / 64, SEQ / 64, BATCH * NHEADS), 256>>>(gq, gk, tau, delta, gS);
        softmax_k<<<BATCH * NHEADS * SEQ, 256>>>(gS);
        av_k<<<dim3(SEQ / 64, BATCH * NHEADS), 256>>>(gS, gv, gattn);

        gemm_tc<<<gProj, 256>>>(gattn, Wo + wOff, bo + bOff, gx, gx,
                                D_MODEL, D_MODEL, 1);
        ln_k<<<ROWS, 128>>>(gx, ln1g + bOff, ln1b + bOff, gxb);
        gemm_tc<<<gFF1, 256>>>(gxb, W1 + w1Off, b1 + b1Off, nullptr, gh,
                               D_FF, D_MODEL, 2);
        gemm_tc<<<gProj, 256>>>(gh, W2 + w2Off, b2 + bOff, gxb, go,
                                D_MODEL, D_FF, 1);
        ln_k<<<ROWS, 128>>>(go, ln2g + bOff, ln2b + bOff, gx);
    }
    ln_k<<<ROWS, 128>>>(gx, lnfg, lnfb, (float*)d_out);
}

// round 4
// speedup vs baseline: 2.8729x; 1.7588x over previous
#include <cuda_runtime.h>
#include <cuda_bf16.h>
#include <math.h>
#include <stdint.h>

#define D_MODEL 512
#define D_FF 2048
#define BATCH 2
#define SEQ 2048
#define NHEADS 8
#define EDIM 64
#define ROWS (BATCH*SEQ)
#define GELU_CF 0.7978845608028654f

// ---------------- scratch ----------------
__device__ float g_x[ROWS*D_MODEL];
__device__ float g_xb[ROWS*D_MODEL];
__device__ float g_q[ROWS*D_MODEL];
__device__ float g_k[ROWS*D_MODEL];
__device__ float g_v[ROWS*D_MODEL];
__device__ float g_attn[ROWS*D_MODEL];
__device__ float g_h[ROWS*D_FF];
__device__ float g_o[ROWS*D_MODEL];

// =======================================================================
// common helpers
// =======================================================================
__device__ __forceinline__ void bsplit2(float x0, float x1, uint32_t& h, uint32_t& l) {
    __nv_bfloat162 hh = __floats2bfloat162_rn(x0, x1);
    float h0 = __bfloat162float(hh.x);
    float h1 = __bfloat162float(hh.y);
    __nv_bfloat162 ll = __floats2bfloat162_rn(x0 - h0, x1 - h1);
    h = *reinterpret_cast<uint32_t*>(&hh);
    l = *reinterpret_cast<uint32_t*>(&ll);
}

__device__ __forceinline__ void mma_bf16(float* c, const uint32_t* a, const uint32_t* b) {
    asm volatile(
        "mma.sync.aligned.m16n8k16.row.col.f32.bf16.bf16.f32 "
        "{%0,%1,%2,%3}, {%4,%5,%6,%7}, {%8,%9}, {%0,%1,%2,%3};"
        : "+f"(c[0]), "+f"(c[1]), "+f"(c[2]), "+f"(c[3])
        : "r"(a[0]), "r"(a[1]), "r"(a[2]), "r"(a[3]), "r"(b[0]), "r"(b[1]));
}

// =======================================================================
// bf16-split tensor-core GEMM (shared body)
// =======================================================================
#define A_PITCH 40
#define B_PITCH 136

__device__ __forceinline__ void gemm_body(
    const float* __restrict__ A, const float* __restrict__ W,
    const float* __restrict__ bias, const float* __restrict__ add,
    float* __restrict__ C, int N, int K, int epi, int bm, int bn,
    uint16_t* sAh, uint16_t* sAl, uint16_t* sBh, uint16_t* sBl)
{
    const int tid = threadIdx.x;
    const int wid = tid >> 5;
    const int lane = tid & 31;
    const int wm = wid & 1;
    const int wn = wid >> 1;
    const int fr = lane >> 2;
    const int fkc = (lane & 3) * 2;

    float acc[4][4][4];
    #pragma unroll
    for (int tm = 0; tm < 4; tm++)
        #pragma unroll
        for (int tn = 0; tn < 4; tn++)
            #pragma unroll
            for (int i = 0; i < 4; i++) acc[tm][tn][i] = 0.f;

    const int nChunks = K >> 5;

    float4 pa[4], pb[4];
    #pragma unroll
    for (int i = 0; i < 4; i++) {
        int idx = tid + i * 256;
        int row = idx >> 3, c4 = idx & 7;
        pa[i] = *(const float4*)(A + (size_t)(bm + row) * K + c4 * 4);
        int kk = idx >> 5, n4 = idx & 31;
        pb[i] = *(const float4*)(W + (size_t)kk * N + bn + n4 * 4);
    }

    for (int chunk = 0; chunk < nChunks; chunk++) {
        #pragma unroll
        for (int i = 0; i < 4; i++) {
            int idx = tid + i * 256;
            int row = idx >> 3, c4 = idx & 7;
            uint32_t h0, l0, h1, l1;
            bsplit2(pa[i].x, pa[i].y, h0, l0);
            bsplit2(pa[i].z, pa[i].w, h1, l1);
            int ao = row * A_PITCH + c4 * 4;
            *(uint32_t*)&sAh[ao]     = h0;  *(uint32_t*)&sAh[ao + 2] = h1;
            *(uint32_t*)&sAl[ao]     = l0;  *(uint32_t*)&sAl[ao + 2] = l1;

            int kk = idx >> 5, n4 = idx & 31;
            bsplit2(pb[i].x, pb[i].y, h0, l0);
            bsplit2(pb[i].z, pb[i].w, h1, l1);
            int bo = kk * B_PITCH + n4 * 4;
            *(uint32_t*)&sBh[bo]     = h0;  *(uint32_t*)&sBh[bo + 2] = h1;
            *(uint32_t*)&sBl[bo]     = l0;  *(uint32_t*)&sBl[bo + 2] = l1;
        }
        __syncthreads();

        if (chunk + 1 < nChunks) {
            int kt = (chunk + 1) << 5;
            #pragma unroll
            for (int i = 0; i < 4; i++) {
                int idx = tid + i * 256;
                int row = idx >> 3, c4 = idx & 7;
                pa[i] = *(const float4*)(A + (size_t)(bm + row) * K + kt + c4 * 4);
                int kk = idx >> 5, n4 = idx & 31;
                pb[i] = *(const float4*)(W + (size_t)(kt + kk) * N + bn + n4 * 4);
            }
        }

        #pragma unroll
        for (int ks = 0; ks < 2; ks++) {
            const int K0 = ks * 16;
            uint32_t ah[4][4], al[4][4];
            #pragma unroll
            for (int tm = 0; tm < 4; tm++) {
                int base = (wm * 64 + tm * 16 + fr) * A_PITCH + K0 + fkc;
                ah[tm][0] = *(const uint32_t*)&sAh[base];
                ah[tm][1] = *(const uint32_t*)&sAh[base + 8 * A_PITCH];
                ah[tm][2] = *(const uint32_t*)&sAh[base + 8];
                ah[tm][3] = *(const uint32_t*)&sAh[base + 8 * A_PITCH + 8];
                al[tm][0] = *(const uint32_t*)&sAl[base];
                al[tm][1] = *(const uint32_t*)&sAl[base + 8 * A_PITCH];
                al[tm][2] = *(const uint32_t*)&sAl[base + 8];
                al[tm][3] = *(const uint32_t*)&sAl[base + 8 * A_PITCH + 8];
            }
            uint32_t bh[4][2], bl[4][2];
            #pragma unroll
            for (int tn = 0; tn < 4; tn++) {
                int n = wn * 32 + tn * 8 + fr;
                int kb = (K0 + fkc) * B_PITCH + n;
                bh[tn][0] = (uint32_t)sBh[kb] | ((uint32_t)sBh[kb + B_PITCH] << 16);
                bh[tn][1] = (uint32_t)sBh[kb + 8 * B_PITCH] | ((uint32_t)sBh[kb + 9 * B_PITCH] << 16);
                bl[tn][0] = (uint32_t)sBl[kb] | ((uint32_t)sBl[kb + B_PITCH] << 16);
                bl[tn][1] = (uint32_t)sBl[kb + 8 * B_PITCH] | ((uint32_t)sBl[kb + 9 * B_PITCH] << 16);
            }
            #pragma unroll
            for (int tm = 0; tm < 4; tm++)
                #pragma unroll
                for (int tn = 0; tn < 4; tn++)
                    mma_bf16(acc[tm][tn], ah[tm], bh[tn]);
            #pragma unroll
            for (int tm = 0; tm < 4; tm++)
                #pragma unroll
                for (int tn = 0; tn < 4; tn++)
                    mma_bf16(acc[tm][tn], ah[tm], bl[tn]);
            #pragma unroll
            for (int tm = 0; tm < 4; tm++)
                #pragma unroll
                for (int tn = 0; tn < 4; tn++)
                    mma_bf16(acc[tm][tn], al[tm], bh[tn]);
        }
        __syncthreads();
    }

    #pragma unroll
    for (int tm = 0; tm < 4; tm++) {
        #pragma unroll
        for (int tn = 0; tn < 4; tn++) {
            int row0 = bm + wm * 64 + tm * 16 + fr;
            int col = bn + wn * 32 + tn * 8 + fkc;
            float b0 = bias[col], b1 = bias[col + 1];
            #pragma unroll
            for (int half = 0; half < 2; half++) {
                int row = row0 + half * 8;
                float v0 = acc[tm][tn][half * 2 + 0] + b0;
                float v1 = acc[tm][tn][half * 2 + 1] + b1;
                if (epi == 1) {
                    const float* ap = add + (size_t)row * N + col;
                    v0 += ap[0]; v1 += ap[1];
                } else if (epi == 2) {
                    float u = v0;
                    v0 = 0.5f * u * (1.0f + tanhf(GELU_CF * (u + 0.044715f * u * u * u)));
                    u = v1;
                    v1 = 0.5f * u * (1.0f + tanhf(GELU_CF * (u + 0.044715f * u * u * u)));
                }
                float2 st = make_float2(v0, v1);
                *(float2*)(C + (size_t)row * N + col) = st;
            }
        }
    }
}

__global__ __launch_bounds__(256) void gemm_tc(
    const float* __restrict__ A, const float* __restrict__ W,
    const float* __restrict__ bias, const float* __restrict__ add,
    float* __restrict__ C, int N, int K, int epi)
{
    __shared__ uint16_t sAh[128 * A_PITCH];
    __shared__ uint16_t sAl[128 * A_PITCH];
    __shared__ uint16_t sBh[32 * B_PITCH];
    __shared__ uint16_t sBl[32 * B_PITCH];
    gemm_body(A, W, bias, add, C, N, K, epi,
              blockIdx.y * 128, blockIdx.x * 128, sAh, sAl, sBh, sBl);
}

// fused QKV: blockIdx.z selects which projection
__global__ __launch_bounds__(256) void gemm_qkv(
    const float* __restrict__ A,
    const float* __restrict__ Wq, const float* __restrict__ Wk, const float* __restrict__ Wv,
    const float* __restrict__ bq, const float* __restrict__ bk, const float* __restrict__ bv,
    float* __restrict__ Cq, float* __restrict__ Ck, float* __restrict__ Cv)
{
    __shared__ uint16_t sAh[128 * A_PITCH];
    __shared__ uint16_t sAl[128 * A_PITCH];
    __shared__ uint16_t sBh[32 * B_PITCH];
    __shared__ uint16_t sBl[32 * B_PITCH];
    const int z = blockIdx.z;
    const float* W = (z == 0) ? Wq : (z == 1) ? Wk : Wv;
    const float* bias = (z == 0) ? bq : (z == 1) ? bk : bv;
    float* C = (z == 0) ? Cq : (z == 1) ? Ck : Cv;
    gemm_body(A, W, bias, nullptr, C, D_MODEL, D_MODEL, 0,
              blockIdx.y * 128, blockIdx.x * 128, sAh, sAl, sBh, sBl);
}

// =======================================================================
// Fused flash attention (causal, scale*(qk*tau + delta))
// Block: 128 query rows x one (b,h). 8 warps x 16 rows. s-tiles of 64 keys.
// =======================================================================
#define KP 72   // u16 pitch for K/V smem tiles

__global__ __launch_bounds__(256) void flash_k(
    const float* __restrict__ Q, const float* __restrict__ Kg,
    const float* __restrict__ Vg,
    const float* __restrict__ tau, const float* __restrict__ delta,
    float* __restrict__ out)
{
    __shared__ uint16_t sKh[64 * KP];
    __shared__ uint16_t sKl[64 * KP];
    __shared__ uint16_t sVh[64 * KP];
    __shared__ uint16_t sVl[64 * KP];

    const int tid = threadIdx.x;
    const int wid = tid >> 5;
    const int lane = tid & 31;
    const int fr = lane >> 2;
    const int fkc = (lane & 3) * 2;

    const int lt = (gridDim.x - 1) - blockIdx.x;   // long blocks first
    const int bh = blockIdx.y;
    const int b = bh >> 3, h = bh & 7;
    const int qrow0 = lt * 128;
    const int rA = qrow0 + wid * 16 + fr;
    const int rB = rA + 8;

    // Q fragments (hi/lo), resident for whole kernel
    uint32_t qh[4][4], ql[4][4];
    #pragma unroll
    for (int ks = 0; ks < 4; ks++) {
        int e0 = ks * 16 + fkc;
        float2 fA0 = *(const float2*)(Q + (size_t)(b * SEQ + rA) * D_MODEL + h * EDIM + e0);
        float2 fB0 = *(const float2*)(Q + (size_t)(b * SEQ + rB) * D_MODEL + h * EDIM + e0);
        float2 fA1 = *(const float2*)(Q + (size_t)(b * SEQ + rA) * D_MODEL + h * EDIM + e0 + 8);
        float2 fB1 = *(const float2*)(Q + (size_t)(b * SEQ + rB) * D_MODEL + h * EDIM + e0 + 8);
        bsplit2(fA0.x, fA0.y, qh[ks][0], ql[ks][0]);
        bsplit2(fB0.x, fB0.y, qh[ks][1], ql[ks][1]);
        bsplit2(fA1.x, fA1.y, qh[ks][2], ql[ks][2]);
        bsplit2(fB1.x, fB1.y, qh[ks][3], ql[ks][3]);
    }

    float oacc[8][4];
    #pragma unroll
    for (int t = 0; t < 8; t++)
        #pragma unroll
        for (int i = 0; i < 4; i++) oacc[t][i] = 0.f;
    float m0 = -3.0e38f, m1 = -3.0e38f;
    float l0 = 0.f, l1 = 0.f;
    const float sct = 0.125f * __ldg(&tau[b]);

    const int nst = 2 * (lt + 1);
    for (int st = 0; st < nst; st++) {
        const int key_base = st * 64;
        // ---- stage K/V tile (64 keys x 64 e) as bf16 hi/lo ----
        #pragma unroll
        for (int i = 0; i < 4; i++) {
            int idx = tid + i * 256;              // over 64 x 16 float4
            int key = idx >> 4, c4 = idx & 15;
            const size_t gof = (size_t)(b * SEQ + key_base + key) * D_MODEL + h * EDIM + c4 * 4;
            float4 kk = *(const float4*)(Kg + gof);
            float4 vv = *(const float4*)(Vg + gof);
            uint32_t h0, lo0, h1, lo1;
            int so = key * KP + c4 * 4;
            bsplit2(kk.x, kk.y, h0, lo0); bsplit2(kk.z, kk.w, h1, lo1);
            *(uint32_t*)&sKh[so] = h0; *(uint32_t*)&sKh[so + 2] = h1;
            *(uint32_t*)&sKl[so] = lo0; *(uint32_t*)&sKl[so + 2] = lo1;
            bsplit2(vv.x, vv.y, h0, lo0); bsplit2(vv.z, vv.w, h1, lo1);
            *(uint32_t*)&sVh[so] = h0; *(uint32_t*)&sVh[so + 2] = h1;
            *(uint32_t*)&sVl[so] = lo0; *(uint32_t*)&sVl[so + 2] = lo1;
        }
        __syncthreads();

        // ---- S = Q K^T over e=64 ----
        float s[8][4];
        #pragma unroll
        for (int t = 0; t < 8; t++)
            #pragma unroll
            for (int i = 0; i < 4; i++) s[t][i] = 0.f;

        #pragma unroll
        for (int ks = 0; ks < 4; ks++) {
            const int K0 = ks * 16;
            uint32_t bhh[8][2], bll[8][2];
            #pragma unroll
            for (int tn = 0; tn < 8; tn++) {
                int key = tn * 8 + fr;
                int base = key * KP + K0 + fkc;
                bhh[tn][0] = *(const uint32_t*)&sKh[base];
                bhh[tn][1] = *(const uint32_t*)&sKh[base + 8];
                bll[tn][0] = *(const uint32_t*)&sKl[base];
                bll[tn][1] = *(const uint32_t*)&sKl[base + 8];
            }
            #pragma unroll
            for (int tn = 0; tn < 8; tn++) {
                mma_bf16(s[tn], qh[ks], bhh[tn]);
                mma_bf16(s[tn], qh[ks], bll[tn]);
                mma_bf16(s[tn], ql[ks], bhh[tn]);
            }
        }

        // ---- scale + bias + causal mask ----
        const bool masked = (key_base + 63) > qrow0;
        #pragma unroll
        for (int tn = 0; tn < 8; tn++) {
            int key = key_base + tn * 8 + fkc;
            float2 dd = *(const float2*)(delta + b * SEQ + key);
            float d0 = 0.125f * dd.x, d1 = 0.125f * dd.y;
            s[tn][0] = fmaf(s[tn][0], sct, d0);
            s[tn][1] = fmaf(s[tn][1], sct, d1);
            s[tn][2] = fmaf(s[tn][2], sct, d0);
            s[tn][3] = fmaf(s[tn][3], sct, d1);
            if (masked) {
                if (key     > rA) s[tn][0] = -1e30f;
                if (key + 1 > rA) s[tn][1] = -1e30f;
                if (key     > rB) s[tn][2] = -1e30f;
                if (key + 1 > rB) s[tn][3] = -1e30f;
            }
        }

        // ---- online softmax ----
        float r0 = -3.0e38f, r1 = -3.0e38f;
        #pragma unroll
        for (int tn = 0; tn < 8; tn++) {
            r0 = fmaxf(r0, fmaxf(s[tn][0], s[tn][1]));
            r1 = fmaxf(r1, fmaxf(s[tn][2], s[tn][3]));
        }
        r0 = fmaxf(r0, __shfl_xor_sync(~0u, r0, 1));
        r0 = fmaxf(r0, __shfl_xor_sync(~0u, r0, 2));
        r1 = fmaxf(r1, __shfl_xor_sync(~0u, r1, 1));
        r1 = fmaxf(r1, __shfl_xor_sync(~0u, r1, 2));
        float mn0 = fmaxf(m0, r0), mn1 = fmaxf(m1, r1);
        float sc0 = expf(m0 - mn0), sc1 = expf(m1 - mn1);
        float sum0 = 0.f, sum1 = 0.f;
        #pragma unroll
        for (int tn = 0; tn < 8; tn++) {
            s[tn][0] = expf(s[tn][0] - mn0); sum0 += s[tn][0];
            s[tn][1] = expf(s[tn][1] - mn0); sum0 += s[tn][1];
            s[tn][2] = expf(s[tn][2] - mn1); sum1 += s[tn][2];
            s[tn][3] = expf(s[tn][3] - mn1); sum1 += s[tn][3];
        }
        sum0 += __shfl_xor_sync(~0u, sum0, 1);
        sum0 += __shfl_xor_sync(~0u, sum0, 2);
        sum1 += __shfl_xor_sync(~0u, sum1, 1);
        sum1 += __shfl_xor_sync(~0u, sum1, 2);
        l0 = l0 * sc0 + sum0; m0 = mn0;
        l1 = l1 * sc1 + sum1; m1 = mn1;
        #pragma unroll
        for (int t = 0; t < 8; t++) {
            oacc[t][0] *= sc0; oacc[t][1] *= sc0;
            oacc[t][2] *= sc1; oacc[t][3] *= sc1;
        }

        // ---- O += P V  (P frags straight from s regs) ----
        #pragma unroll
        for (int kc = 0; kc < 4; kc++) {
            uint32_t ah[4], al[4];
            bsplit2(s[2*kc][0],   s[2*kc][1],   ah[0], al[0]);
            bsplit2(s[2*kc][2],   s[2*kc][3],   ah[1], al[1]);
            bsplit2(s[2*kc+1][0], s[2*kc+1][1], ah[2], al[2]);
            bsplit2(s[2*kc+1][2], s[2*kc+1][3], ah[3], al[3]);
            #pragma unroll
            for (int tn2 = 0; tn2 < 8; tn2++) {
                int n = tn2 * 8 + fr;
                int k0 = kc * 16 + fkc;
                uint32_t b0h = (uint32_t)sVh[k0*KP + n] | ((uint32_t)sVh[(k0+1)*KP + n] << 16);
                uint32_t b1h = (uint32_t)sVh[(k0+8)*KP + n] | ((uint32_t)sVh[(k0+9)*KP + n] << 16);
                uint32_t b0l = (uint32_t)sVl[k0*KP + n] | ((uint32_t)sVl[(k0+1)*KP + n] << 16);
                uint32_t b1l = (uint32_t)sVl[(k0+8)*KP + n] | ((uint32_t)sVl[(k0+9)*KP + n] << 16);
                uint32_t bvh[2] = {b0h, b1h}, bvl[2] = {b0l, b1l};
                mma_bf16(oacc[tn2], ah, bvh);
                mma_bf16(oacc[tn2], ah, bvl);
                mma_bf16(oacc[tn2], al, bvh);
            }
        }
        __syncthreads();
    }

    // ---- write O / l ----
    const float inv0 = 1.0f / l0, inv1 = 1.0f / l1;
    #pragma unroll
    for (int tn2 = 0; tn2 < 8; tn2++) {
        int col = h * EDIM + tn2 * 8 + fkc;
        float2 vA = make_float2(oacc[tn2][0] * inv0, oacc[tn2][1] * inv0);
        float2 vB = make_float2(oacc[tn2][2] * inv1, oacc[tn2][3] * inv1);
        *(float2*)(out + (size_t)(b * SEQ + rA) * D_MODEL + col) = vA;
        *(float2*)(out + (size_t)(b * SEQ + rB) * D_MODEL + col) = vB;
    }
}

// ---------------- LayerNorm ----------------
__global__ __launch_bounds__(128) void ln_k(
    const float* __restrict__ x, const float* __restrict__ g,
    const float* __restrict__ bb, float* __restrict__ y)
{
    const int row = blockIdx.x;
    const float* p = x + (size_t)row * D_MODEL;
    const int tid = threadIdx.x;
    float v[4];
    float s = 0.f;
    #pragma unroll
    for (int i = 0; i < 4; i++) { v[i] = p[tid + i * 128]; s += v[i]; }
    __shared__ float sh[4];
    #pragma unroll
    for (int o = 16; o > 0; o >>= 1) s += __shfl_xor_sync(~0u, s, o);
    if ((tid & 31) == 0) sh[tid >> 5] = s;
    __syncthreads();
    s = sh[0] + sh[1] + sh[2] + sh[3];
    const float mean = s * (1.0f / (float)D_MODEL);
    float vs = 0.f;
    #pragma unroll
    for (int i = 0; i < 4; i++) { float d = v[i] - mean; vs += d * d; }
    #pragma unroll
    for (int o = 16; o > 0; o >>= 1) vs += __shfl_xor_sync(~0u, vs, o);
    __syncthreads();
    if ((tid & 31) == 0) sh[tid >> 5] = vs;
    __syncthreads();
    vs = sh[0] + sh[1] + sh[2] + sh[3];
    const float rstd = rsqrtf(vs * (1.0f / (float)D_MODEL) + 1e-5f);
    #pragma unroll
    for (int i = 0; i < 4; i++) {
        int col = tid + i * 128;
        y[(size_t)row * D_MODEL + col] = (v[i] - mean) * rstd * g[col] + bb[col];
    }
}

// ---------------- orchestration ----------------
extern "C" void kernel_launch(void* const* d_in, const int* in_sizes, int n_in,
                              void* d_out, int out_size)
{
    const float* x_in  = (const float*)d_in[0];
    const float* tau   = (const float*)d_in[1];
    const float* delta = (const float*)d_in[2];
    const float* Wq = (const float*)d_in[4];
    const float* bq = (const float*)d_in[5];
    const float* Wk = (const float*)d_in[6];
    const float* bk = (const float*)d_in[7];
    const float* Wv = (const float*)d_in[8];
    const float* bv = (const float*)d_in[9];
    const float* Wo = (const float*)d_in[10];
    const float* bo = (const float*)d_in[11];
    const float* W1 = (const float*)d_in[12];
    const float* b1 = (const float*)d_in[13];
    const float* W2 = (const float*)d_in[14];
    const float* b2 = (const float*)d_in[15];
    const float* ln1g = (const float*)d_in[16];
    const float* ln1b = (const float*)d_in[17];
    const float* ln2g = (const float*)d_in[18];
    const float* ln2b = (const float*)d_in[19];
    const float* lnfg = (const float*)d_in[20];
    const float* lnfb = (const float*)d_in[21];

    float *gx, *gxb, *gq, *gk, *gv, *gattn, *gh, *go;
    cudaGetSymbolAddress((void**)&gx,    g_x);
    cudaGetSymbolAddress((void**)&gxb,   g_xb);
    cudaGetSymbolAddress((void**)&gq,    g_q);
    cudaGetSymbolAddress((void**)&gk,    g_k);
    cudaGetSymbolAddress((void**)&gv,    g_v);
    cudaGetSymbolAddress((void**)&gattn, g_attn);
    cudaGetSymbolAddress((void**)&gh,    g_h);
    cudaGetSymbolAddress((void**)&go,    g_o);

    cudaMemcpyAsync(gx, x_in, sizeof(float) * ROWS * D_MODEL,
                    cudaMemcpyDeviceToDevice, 0);

    const dim3 gProj(D_MODEL / 128, ROWS / 128);       // (4, 32)
    const dim3 gQKV(D_MODEL / 128, ROWS / 128, 3);     // (4, 32, 3)
    const dim3 gFF1(D_FF / 128, ROWS / 128);           // (16, 32)
    const dim3 gFlash(SEQ / 128, BATCH * NHEADS);      // (16, 16)

    for (int l = 0; l < 2; l++) {
        const size_t wOff  = (size_t)l * D_MODEL * D_MODEL;
        const size_t bOff  = (size_t)l * D_MODEL;
        const size_t w1Off = (size_t)l * D_MODEL * D_FF;
        const size_t b1Off = (size_t)l * D_FF;
        const size_t w2Off = (size_t)l * D_FF * D_MODEL;

        gemm_qkv<<<gQKV, 256>>>(gx, Wq + wOff, Wk + wOff, Wv + wOff,
                                bq + bOff, bk + bOff, bv + bOff, gq, gk, gv);

        flash_k<<<gFlash, 256>>>(gq, gk, gv, tau, delta, gattn);

        gemm_tc<<<gProj, 256>>>(gattn, Wo + wOff, bo + bOff, gx, gx,
                                D_MODEL, D_MODEL, 1);
        ln_k<<<ROWS, 128>>>(gx, ln1g + bOff, ln1b + bOff, gxb);
        gemm_tc<<<gFF1, 256>>>(gxb, W1 + w1Off, b1 + b1Off, nullptr, gh,
                               D_FF, D_MODEL, 2);
        gemm_tc<<<gProj, 256>>>(gh, W2 + w2Off, b2 + bOff, gxb, go,
                                D_MODEL, D_FF, 1);
        ln_k<<<ROWS, 128>>>(go, ln2g + bOff, ln2b + bOff, gx);
    }
    ln_k<<<ROWS, 128>>>(gx, lnfg, lnfb, (float*)d_out);
}